// round 5
// baseline (speedup 1.0000x reference)
#include <cuda_runtime.h>
#include <math.h>

#define BATCH 32
#define NDIM  325
#define T1D   288
#define T3D   864
#define TLEN  2016
#define KSZ   577
#define FREQ  513
#define LFFT  1024
#define FEAT  (BATCH*T3D*NDIM)
#define MROWS (BATCH*T3D)

__device__ float  g_buf0[FEAT];
__device__ float  g_buf1[FEAT];
__device__ float  g_s1[FEAT];
__device__ float  g_s2[FEAT];
__device__ float2 g_ghat[(size_t)BATCH*NDIM*FREQ];
__device__ float2 g_what[(size_t)NDIM*NDIM*FREQ];
__device__ float2 g_ohat[(size_t)BATCH*NDIM*FREQ];
__device__ float2 g_twf[LFFT];
__device__ float2 g_twi[LFFT];

__global__ void init_tw_kernel() {
    int idx = blockIdx.x * blockDim.x + threadIdx.x;
    if (idx >= LFFT) return;
    if (idx == 0) { g_twf[0] = make_float2(1.f,0.f); g_twi[0] = make_float2(1.f,0.f); return; }
    int Ns = 1 << (31 - __clz(idx));
    float ang = 3.14159265358979323846f * (float)(idx - Ns) / (float)Ns;
    float s, c; sincosf(ang, &s, &c);
    g_twf[idx] = make_float2(c, -s);
    g_twi[idx] = make_float2(c,  s);
}

__global__ void gather_kernel(const float* __restrict__ infeat,
                              const float* __restrict__ x,
                              const int* __restrict__ week,
                              const int* __restrict__ hour) {
    int idx = blockIdx.x * blockDim.x + threadIdx.x;
    if (idx >= FEAT) return;
    int d = idx % NDIM, t = idx / NDIM;
    int m = t % T3D, b = t / T3D;
    float v;
    if (m >= T1D && m < 2 * T1D) {
        v = infeat[(b * NDIM + d) * T1D + (m - T1D)];
    } else {
        int s  = week[b] * T1D + hour[b];
        int tt = (m + s + (TLEN - T1D)) % TLEN;
        v = x[tt * NDIM + d];
    }
    g_buf0[idx] = v;
}

// C[MxN] = A[MxK]*B[KxN], BM=128 BN=64 BK=8, 256 thr, 8x4/thread
__global__ __launch_bounds__(256)
void gemm_kernel(const float* __restrict__ A, const float* __restrict__ B,
                 float* __restrict__ C, int M, int K, int N) {
    __shared__ float As[8][128];
    __shared__ float Bs[8][64];
    int bm = blockIdx.x * 128, bn = blockIdx.y * 64, tid = threadIdx.x;
    int tm = (tid >> 4) * 8, tn = (tid & 15) * 4;
    float acc[8][4];
#pragma unroll
    for (int i = 0; i < 8; i++)
#pragma unroll
        for (int j = 0; j < 4; j++) acc[i][j] = 0.f;
    for (int k0 = 0; k0 < K; k0 += 8) {
        {
            int row = tid >> 1, kq = (tid & 1) * 4;
            const float* ap = A + (size_t)(bm + row) * K + k0 + kq;
#pragma unroll
            for (int j = 0; j < 4; j++)
                As[kq + j][row] = (k0 + kq + j < K) ? ap[j] : 0.f;
        }
        {
            int nn = tid & 63, kb = tid >> 6;
#pragma unroll
            for (int j = 0; j < 2; j++) {
                int kk = kb + j * 4;
                float v = 0.f;
                if (k0 + kk < K && bn + nn < N) v = B[(size_t)(k0 + kk) * N + bn + nn];
                Bs[kk][nn] = v;
            }
        }
        __syncthreads();
#pragma unroll
        for (int kk = 0; kk < 8; kk++) {
            float4 a0 = *(const float4*)&As[kk][tm];
            float4 a1 = *(const float4*)&As[kk][tm + 4];
            float4 b0 = *(const float4*)&Bs[kk][tn];
            float av[8] = {a0.x,a0.y,a0.z,a0.w,a1.x,a1.y,a1.z,a1.w};
            float bv[4] = {b0.x,b0.y,b0.z,b0.w};
#pragma unroll
            for (int i = 0; i < 8; i++)
#pragma unroll
                for (int j = 0; j < 4; j++)
                    acc[i][j] = fmaf(av[i], bv[j], acc[i][j]);
        }
        __syncthreads();
    }
#pragma unroll
    for (int i = 0; i < 8; i++) {
        size_t rr = bm + tm + i;
#pragma unroll
        for (int j = 0; j < 4; j++) {
            int cc = bn + tn + j;
            if (cc < N) C[rr * N + cc] = acc[i][j];
        }
    }
}

// banded-A stencil + bias + tanh*sigmoid gate
__global__ void stencil_kernel(const float* __restrict__ S1, const float* __restrict__ S2,
                               const float* __restrict__ bt, const float* __restrict__ bs,
                               float* __restrict__ outp) {
    int idx = blockIdx.x * blockDim.x + threadIdx.x;
    if (idx >= FEAT) return;
    int o = idx % NDIM, bm = idx / NDIM;
    int m = bm % T3D;
    size_t base = (size_t)(bm - m) * NDIM + o;
    float dm = rsqrtf((float)(1 + min(m, 3) + min(T3D - 1 - m, 3)));
    int lo = (m > 3) ? m - 3 : 0;
    int hi = (m < T3D - 4) ? m + 3 : T3D - 1;
    float s1 = 0.f, s2 = 0.f;
    for (int n = lo; n <= hi; n++) {
        float dn = rsqrtf((float)(1 + min(n, 3) + min(T3D - 1 - n, 3)));
        float w = dm * dn;
        s1 += w * S1[base + (size_t)n * NDIM];
        s2 += w * S2[base + (size_t)n * NDIM];
    }
    float gv = tanhf(s1 + bt[o]);
    float sv = 1.f / (1.f + expf(-(s2 + bs[o])));
    outp[idx] = gv * sv;
}

// in-block Stockham radix-2 FFT len 1024, 512 threads
__device__ __forceinline__ float2* fft1024(float2* a, float2* b, const float2* tw) {
    int tid = threadIdx.x;
    float2 *src = a, *dst = b;
#pragma unroll
    for (int Ns = 1; Ns < LFFT; Ns <<= 1) {
        int r = tid & (Ns - 1);
        float2 v0 = src[tid], v1 = src[tid + 512];
        float2 w = tw[Ns + r];
        float2 p = make_float2(w.x*v1.x - w.y*v1.y, w.x*v1.y + w.y*v1.x);
        int oi = ((tid - r) << 1) + r;
        dst[oi]      = make_float2(v0.x + p.x, v0.y + p.y);
        dst[oi + Ns] = make_float2(v0.x - p.x, v0.y - p.y);
        __syncthreads();
        float2* t2 = src; src = dst; dst = t2;
    }
    return src;
}

__global__ __launch_bounds__(512)
void fft_w_kernel(const float* __restrict__ cw) {
    __shared__ float2 bufA[LFFT], bufB[LFFT], tws[LFFT];
    int tid = threadIdx.x, oi = blockIdx.x;
    const float* src = cw + (size_t)oi * KSZ;
    for (int t = tid; t < LFFT; t += 512) {
        tws[t]  = g_twf[t];
        bufA[t] = make_float2(t < KSZ ? src[t] : 0.f, 0.f);
    }
    __syncthreads();
    float2* res = fft1024(bufA, bufB, tws);
    float2* dst = g_what + (size_t)oi * FREQ;
    for (int f = tid; f < FREQ; f += 512) dst[f] = res[f];
}

__global__ __launch_bounds__(512)
void fft_g_kernel(const float* __restrict__ G) {
    __shared__ float2 bufA[LFFT], bufB[LFFT], tws[LFFT];
    int tid = threadIdx.x, bi = blockIdx.x;
    int b = bi / NDIM, i = bi % NDIM;
    const float* src = G + (size_t)b * T3D * NDIM + i;
    for (int t = tid; t < LFFT; t += 512) {
        tws[t]  = g_twf[t];
        bufA[t] = make_float2(t < T3D ? src[(size_t)t * NDIM] : 0.f, 0.f);
    }
    __syncthreads();
    float2* res = fft1024(bufA, bufB, tws);
    float2* dst = g_ghat + (size_t)bi * FREQ;
    for (int f = tid; f < FREQ; f += 512) dst[f] = res[f];
}

// Ohat[b,o,f] = sum_i Ghat[b,i,f]*conj(What[o,i,f]); 4f x 32o x 32b per block
__global__ __launch_bounds__(256)
void fgemm_kernel() {
    __shared__ float2 Gs[8][4][33];
    __shared__ float2 Ws[8][4][33];
    int f0 = blockIdx.x * 4, o0 = blockIdx.y * 32, tid = threadIdx.x;
    int tf = tid & 3, to = (tid >> 2) & 7, tb = tid >> 5;
    float2 acc[4][4];
#pragma unroll
    for (int i = 0; i < 4; i++)
#pragma unroll
        for (int j = 0; j < 4; j++) acc[i][j] = make_float2(0.f, 0.f);
    for (int i0 = 0; i0 < NDIM; i0 += 8) {
        for (int l = tid; l < 1024; l += 256) {
            int lf = l & 3, li = (l >> 2) & 7, lb = l >> 5;
            int f = f0 + lf, ii = i0 + li;
            float2 g = make_float2(0.f, 0.f), w = make_float2(0.f, 0.f);
            if (f < FREQ && ii < NDIM) {
                g = g_ghat[((size_t)lb * NDIM + ii) * FREQ + f];
                int o = o0 + lb;
                if (o < NDIM) w = g_what[((size_t)o * NDIM + ii) * FREQ + f];
            }
            Gs[li][lf][lb] = g;
            Ws[li][lf][lb] = w;
        }
        __syncthreads();
#pragma unroll
        for (int i2 = 0; i2 < 8; i2++) {
            float2 gv[4], wv[4];
#pragma unroll
            for (int q = 0; q < 4; q++) gv[q] = Gs[i2][tf][tb * 4 + q];
#pragma unroll
            for (int q = 0; q < 4; q++) wv[q] = Ws[i2][tf][to * 4 + q];
#pragma unroll
            for (int bi = 0; bi < 4; bi++)
#pragma unroll
                for (int oi = 0; oi < 4; oi++) {
                    acc[bi][oi].x += gv[bi].x * wv[oi].x + gv[bi].y * wv[oi].y;
                    acc[bi][oi].y += gv[bi].y * wv[oi].x - gv[bi].x * wv[oi].y;
                }
        }
        __syncthreads();
    }
    int f = f0 + tf;
    if (f >= FREQ) return;
#pragma unroll
    for (int bi = 0; bi < 4; bi++)
#pragma unroll
        for (int oi = 0; oi < 4; oi++) {
            int b = tb * 4 + bi, o = o0 + to * 4 + oi;
            if (o < NDIM)
                g_ohat[((size_t)b * NDIM + o) * FREQ + f] = acc[bi][oi];
        }
}

__global__ __launch_bounds__(512)
void ifft_kernel(const float* __restrict__ cb, float* __restrict__ outp) {
    __shared__ float2 bufA[LFFT], bufB[LFFT], tws[LFFT];
    int tid = threadIdx.x, bo = blockIdx.x;
    int o = bo % NDIM;
    const float2* src = g_ohat + (size_t)bo * FREQ;
    for (int f = tid; f < LFFT; f += 512) {
        tws[f] = g_twi[f];
        float2 v;
        if (f < FREQ) v = src[f];
        else { float2 u = src[LFFT - f]; v = make_float2(u.x, -u.y); }
        bufA[f] = v;
    }
    __syncthreads();
    float2* res = fft1024(bufA, bufB, tws);
    float bias = cb[o];
    for (int t = tid; t < T1D; t += 512)
        outp[(size_t)bo * T1D + t] = res[t].x * (1.f / 1024.f) + bias;
}

extern "C" void kernel_launch(void* const* d_in, const int* in_sizes, int n_in,
                              void* d_out, int out_size) {
    const float* infeat = (const float*)d_in[0];
    const float* x    = (const float*)d_in[1];
    const float* w1   = (const float*)d_in[2];  const float* b1  = (const float*)d_in[3];
    const float* w11  = (const float*)d_in[4];  const float* b11 = (const float*)d_in[5];
    const float* w2   = (const float*)d_in[6];  const float* b2  = (const float*)d_in[7];
    const float* w22  = (const float*)d_in[8];  const float* b22 = (const float*)d_in[9];
    const float* w3   = (const float*)d_in[10]; const float* b3  = (const float*)d_in[11];
    const float* w33  = (const float*)d_in[12]; const float* b33 = (const float*)d_in[13];
    const float* cw   = (const float*)d_in[14]; const float* cb  = (const float*)d_in[15];
    const int*   week = (const int*)d_in[16];   const int*   hour = (const int*)d_in[17];
    float* outp = (float*)d_out;

    float *buf0, *buf1, *s1, *s2;
    cudaGetSymbolAddress((void**)&buf0, g_buf0);
    cudaGetSymbolAddress((void**)&buf1, g_buf1);
    cudaGetSymbolAddress((void**)&s1,   g_s1);
    cudaGetSymbolAddress((void**)&s2,   g_s2);

    const int eb = (FEAT + 255) / 256;
    dim3 gg(MROWS / 128, (NDIM + 63) / 64);

    init_tw_kernel<<<2, 512>>>();
    gather_kernel<<<eb, 256>>>(infeat, x, week, hour);

    gemm_kernel<<<gg, 256>>>(buf0, w1,  s1, MROWS, NDIM, NDIM);
    gemm_kernel<<<gg, 256>>>(buf0, w11, s2, MROWS, NDIM, NDIM);
    stencil_kernel<<<eb, 256>>>(s1, s2, b1, b11, buf1);

    gemm_kernel<<<gg, 256>>>(buf1, w2,  s1, MROWS, NDIM, NDIM);
    gemm_kernel<<<gg, 256>>>(buf1, w22, s2, MROWS, NDIM, NDIM);
    stencil_kernel<<<eb, 256>>>(s1, s2, b2, b22, buf0);

    gemm_kernel<<<gg, 256>>>(buf0, w3,  s1, MROWS, NDIM, NDIM);
    gemm_kernel<<<gg, 256>>>(buf0, w33, s2, MROWS, NDIM, NDIM);
    stencil_kernel<<<eb, 256>>>(s1, s2, b3, b33, buf1);

    fft_g_kernel<<<BATCH * NDIM, 512>>>(buf1);
    fft_w_kernel<<<NDIM * NDIM, 512>>>(cw);
    fgemm_kernel<<<dim3((FREQ + 3) / 4, (NDIM + 31) / 32), 256>>>();
    ifft_kernel<<<BATCH * NDIM, 512>>>(cb, outp);
}

// round 11
// speedup vs baseline: 1.2655x; 1.2655x over previous
#include <cuda_runtime.h>
#include <cuda_bf16.h>
#include <stdint.h>
#include <math.h>

#define BATCH 32
#define NDIM  325
#define T1D   288
#define T3D   864
#define TLEN  2016
#define KSZ   577
#define FREQ  513
#define LFFT  1024
#define FEAT  (BATCH*T3D*NDIM)
#define MROWS (BATCH*T3D)
#define KP    384

// ---------------- static device scratch (no allocs allowed) ----------------
__device__ float  g_buf0[FEAT];
__device__ float  g_buf1[FEAT];
__device__ float  g_s1[FEAT];
__device__ float  g_s2[FEAT];
__device__ __nv_bfloat16 g_ah0[(size_t)MROWS*KP];
__device__ __nv_bfloat16 g_al0[(size_t)MROWS*KP];
__device__ __nv_bfloat16 g_ah1[(size_t)MROWS*KP];
__device__ __nv_bfloat16 g_al1[(size_t)MROWS*KP];
__device__ __nv_bfloat16 g_wth[6*KP*KP];   // W^T padded: [gemm][n][k]
__device__ __nv_bfloat16 g_wtl[6*KP*KP];
__device__ float2 g_ghat[(size_t)BATCH*NDIM*FREQ];
__device__ float2 g_what[(size_t)NDIM*NDIM*FREQ];
__device__ float2 g_ohat[(size_t)BATCH*NDIM*FREQ];
__device__ float2 g_twf[LFFT];
__device__ float2 g_twi[LFFT];

// ---------------- stage 1: roll einsums collapse to a gather (+bf16 split) ----------------
__global__ void gather_split_kernel(const float* __restrict__ infeat,
                                    const float* __restrict__ x,
                                    const int* __restrict__ week,
                                    const int* __restrict__ hour) {
    int idx = blockIdx.x * blockDim.x + threadIdx.x;
    if (idx >= MROWS * KP) return;
    int d = idx % KP, t = idx / KP;
    int m = t % T3D, b = t / T3D;
    float v = 0.f;
    if (d < NDIM) {
        if (m >= T1D && m < 2 * T1D) {
            v = infeat[(b * NDIM + d) * T1D + (m - T1D)];
        } else {
            int s  = week[b] * T1D + hour[b];
            int tt = (m + s + (TLEN - T1D)) % TLEN;
            v = x[tt * NDIM + d];
        }
    }
    __nv_bfloat16 h = __float2bfloat16(v);
    g_ah0[idx] = h;
    g_al0[idx] = __float2bfloat16(v - __bfloat162float(h));
}

// weight prep: transposed, padded to [KP x KP], split hi/lo
struct W6 { const float* p[6]; };
__global__ void wsplit_kernel(W6 wp) {
    int idx = blockIdx.x * blockDim.x + threadIdx.x;
    if (idx >= 6 * KP * KP) return;
    int g = idx / (KP * KP);
    int r = idx - g * KP * KP;
    int n = r / KP, k = r - n * KP;
    float v = (n < NDIM && k < NDIM) ? wp.p[g][k * NDIM + n] : 0.f;
    __nv_bfloat16 h = __float2bfloat16(v);
    g_wth[idx] = h;
    g_wtl[idx] = __float2bfloat16(v - __bfloat162float(h));
}

// ---------------- split-bf16 mma.sync GEMM: C[MROWSxNDIM] = A[MROWSxKP] * W[KPxNDIM] ----------------
// W passed as W^T [NDIM pad KP][KP]. Block tile 128x64, 8 warps of 32x32 each.
// K staged in 64-wide chunks: Ah,Al [128][64], Bh,Bl [64][64] in dynamic smem.
#define SMS    72                 // smem row stride in bf16 (64 + 8 pad)
#define OFF_AH 0
#define OFF_AL (128*SMS*2)        // 18432
#define OFF_BH (2*128*SMS*2)      // 36864
#define OFF_BL (2*128*SMS*2 + 64*SMS*2)
#define MMA_SMEM (2*128*SMS*2 + 2*64*SMS*2)   // 55296

#define MMA16816(c, a, b) \
    asm volatile("mma.sync.aligned.m16n8k16.row.col.f32.bf16.bf16.f32 " \
        "{%0,%1,%2,%3}, {%4,%5,%6,%7}, {%8,%9}, {%0,%1,%2,%3};" \
        : "+f"((c)[0]), "+f"((c)[1]), "+f"((c)[2]), "+f"((c)[3]) \
        : "r"((a)[0]), "r"((a)[1]), "r"((a)[2]), "r"((a)[3]), "r"((b)[0]), "r"((b)[1]))

__global__ __launch_bounds__(256)
void gemm_mma(const __nv_bfloat16* __restrict__ Ah, const __nv_bfloat16* __restrict__ Al,
              const __nv_bfloat16* __restrict__ Bh, const __nv_bfloat16* __restrict__ Bl,
              float* __restrict__ C) {
    extern __shared__ char smem[];
    __nv_bfloat16* sAh = (__nv_bfloat16*)(smem + OFF_AH);
    __nv_bfloat16* sAl = (__nv_bfloat16*)(smem + OFF_AL);
    __nv_bfloat16* sBh = (__nv_bfloat16*)(smem + OFF_BH);
    __nv_bfloat16* sBl = (__nv_bfloat16*)(smem + OFF_BL);
    int tid = threadIdx.x, wid = tid >> 5, lane = tid & 31;
    int bm = blockIdx.x * 128, n0 = blockIdx.y * 64;
    int wrow = (wid >> 1) * 32, wcol = (wid & 1) * 32;
    int lr = lane >> 2;            // 0..7
    int lc = (lane & 3) * 2;       // 0,2,4,6

    float acc[2][4][4];
#pragma unroll
    for (int mt = 0; mt < 2; mt++)
#pragma unroll
        for (int nt = 0; nt < 4; nt++)
#pragma unroll
            for (int q = 0; q < 4; q++) acc[mt][nt][q] = 0.f;

    for (int k0 = 0; k0 < KP; k0 += 64) {
        __syncthreads();
        // stage A chunks: 128 rows x 64 k  (8 uint4 per row)
        for (int i = tid; i < 1024; i += 256) {
            int r = i >> 3, q = i & 3, half = (i >> 2) & 1;   // 2 halves x 4 quads
            int qq = half * 4 + q;
            *(uint4*)(sAh + r * SMS + qq * 8) =
                *(const uint4*)(Ah + (size_t)(bm + r) * KP + k0 + qq * 8);
            *(uint4*)(sAl + r * SMS + qq * 8) =
                *(const uint4*)(Al + (size_t)(bm + r) * KP + k0 + qq * 8);
        }
        // stage B chunks: 64 rows (n) x 64 k
        for (int i = tid; i < 512; i += 256) {
            int r = i >> 3, qq = i & 7;
            *(uint4*)(sBh + r * SMS + qq * 8) =
                *(const uint4*)(Bh + (size_t)(n0 + r) * KP + k0 + qq * 8);
            *(uint4*)(sBl + r * SMS + qq * 8) =
                *(const uint4*)(Bl + (size_t)(n0 + r) * KP + k0 + qq * 8);
        }
        __syncthreads();

#pragma unroll
        for (int ks = 0; ks < 4; ks++) {
            int kk = ks * 16;
            uint32_t ah[2][4], al[2][4], bh[4][2], bl[4][2];
#pragma unroll
            for (int mt = 0; mt < 2; mt++) {
                int r = wrow + mt * 16 + lr;
                ah[mt][0] = *(const uint32_t*)(sAh + r * SMS + kk + lc);
                ah[mt][1] = *(const uint32_t*)(sAh + (r + 8) * SMS + kk + lc);
                ah[mt][2] = *(const uint32_t*)(sAh + r * SMS + kk + lc + 8);
                ah[mt][3] = *(const uint32_t*)(sAh + (r + 8) * SMS + kk + lc + 8);
                al[mt][0] = *(const uint32_t*)(sAl + r * SMS + kk + lc);
                al[mt][1] = *(const uint32_t*)(sAl + (r + 8) * SMS + kk + lc);
                al[mt][2] = *(const uint32_t*)(sAl + r * SMS + kk + lc + 8);
                al[mt][3] = *(const uint32_t*)(sAl + (r + 8) * SMS + kk + lc + 8);
            }
#pragma unroll
            for (int nt = 0; nt < 4; nt++) {
                int n = wcol + nt * 8 + lr;
                bh[nt][0] = *(const uint32_t*)(sBh + n * SMS + kk + lc);
                bh[nt][1] = *(const uint32_t*)(sBh + n * SMS + kk + lc + 8);
                bl[nt][0] = *(const uint32_t*)(sBl + n * SMS + kk + lc);
                bl[nt][1] = *(const uint32_t*)(sBl + n * SMS + kk + lc + 8);
            }
#pragma unroll
            for (int mt = 0; mt < 2; mt++)
#pragma unroll
                for (int nt = 0; nt < 4; nt++) {
                    MMA16816(acc[mt][nt], ah[mt], bh[nt]);
                    MMA16816(acc[mt][nt], ah[mt], bl[nt]);
                    MMA16816(acc[mt][nt], al[mt], bh[nt]);
                }
        }
    }

    // epilogue: c0,c1 at (row, col..col+1); c2,c3 at (row+8, col..col+1)
#pragma unroll
    for (int mt = 0; mt < 2; mt++) {
        size_t row = (size_t)bm + wrow + mt * 16 + lr;
#pragma unroll
        for (int nt = 0; nt < 4; nt++) {
            int col = n0 + wcol + nt * 8 + lc;
            if (col < NDIM)     C[row * NDIM + col]           = acc[mt][nt][0];
            if (col + 1 < NDIM) C[row * NDIM + col + 1]       = acc[mt][nt][1];
            if (col < NDIM)     C[(row + 8) * NDIM + col]     = acc[mt][nt][2];
            if (col + 1 < NDIM) C[(row + 8) * NDIM + col + 1] = acc[mt][nt][3];
        }
    }
}

// ---------------- banded-A stencil + gate (+bf16 split of output) ----------------
__global__ void stencil_split_kernel(const float* __restrict__ S1, const float* __restrict__ S2,
                                     const float* __restrict__ bt, const float* __restrict__ bs,
                                     float* __restrict__ outp,
                                     __nv_bfloat16* __restrict__ oh, __nv_bfloat16* __restrict__ ol) {
    int idx = blockIdx.x * blockDim.x + threadIdx.x;
    if (idx >= MROWS * KP) return;
    int o = idx % KP, bm = idx / KP;
    float val = 0.f;
    if (o < NDIM) {
        int m = bm % T3D;
        size_t base = (size_t)(bm - m) * NDIM + o;
        float dm = rsqrtf((float)(1 + min(m, 3) + min(T3D - 1 - m, 3)));
        int lo = (m > 3) ? m - 3 : 0;
        int hi = (m < T3D - 4) ? m + 3 : T3D - 1;
        float s1 = 0.f, s2 = 0.f;
        for (int n = lo; n <= hi; n++) {
            float dn = rsqrtf((float)(1 + min(n, 3) + min(T3D - 1 - n, 3)));
            float w = dm * dn;
            s1 += w * S1[base + (size_t)n * NDIM];
            s2 += w * S2[base + (size_t)n * NDIM];
        }
        float gv = tanhf(s1 + bt[o]);
        float sv = 1.f / (1.f + expf(-(s2 + bs[o])));
        val = gv * sv;
        outp[(size_t)bm * NDIM + o] = val;
    }
    __nv_bfloat16 h = __float2bfloat16(val);
    oh[idx] = h;
    ol[idx] = __float2bfloat16(val - __bfloat162float(h));
}

// ---------------- FFT machinery (round-5 proven) ----------------
__global__ void init_tw_kernel() {
    int idx = blockIdx.x * blockDim.x + threadIdx.x;
    if (idx >= LFFT) return;
    if (idx == 0) { g_twf[0] = make_float2(1.f,0.f); g_twi[0] = make_float2(1.f,0.f); return; }
    int Ns = 1 << (31 - __clz(idx));
    float ang = 3.14159265358979323846f * (float)(idx - Ns) / (float)Ns;
    float s, c; sincosf(ang, &s, &c);
    g_twf[idx] = make_float2(c, -s);
    g_twi[idx] = make_float2(c,  s);
}

__device__ __forceinline__ float2* fft1024(float2* a, float2* b, const float2* tw) {
    int tid = threadIdx.x;
    float2 *src = a, *dst = b;
#pragma unroll
    for (int Ns = 1; Ns < LFFT; Ns <<= 1) {
        int r = tid & (Ns - 1);
        float2 v0 = src[tid], v1 = src[tid + 512];
        float2 w = tw[Ns + r];
        float2 p = make_float2(w.x*v1.x - w.y*v1.y, w.x*v1.y + w.y*v1.x);
        int oi = ((tid - r) << 1) + r;
        dst[oi]      = make_float2(v0.x + p.x, v0.y + p.y);
        dst[oi + Ns] = make_float2(v0.x - p.x, v0.y - p.y);
        __syncthreads();
        float2* t2 = src; src = dst; dst = t2;
    }
    return src;
}

__global__ __launch_bounds__(512)
void fft_w_kernel(const float* __restrict__ cw) {
    __shared__ float2 bufA[LFFT], bufB[LFFT], tws[LFFT];
    int tid = threadIdx.x, oi = blockIdx.x;
    const float* src = cw + (size_t)oi * KSZ;
    for (int t = tid; t < LFFT; t += 512) {
        tws[t]  = g_twf[t];
        bufA[t] = make_float2(t < KSZ ? src[t] : 0.f, 0.f);
    }
    __syncthreads();
    float2* res = fft1024(bufA, bufB, tws);
    float2* dst = g_what + (size_t)oi * FREQ;
    for (int f = tid; f < FREQ; f += 512) dst[f] = res[f];
}

__global__ __launch_bounds__(512)
void fft_g_kernel(const float* __restrict__ G) {
    __shared__ float2 bufA[LFFT], bufB[LFFT], tws[LFFT];
    int tid = threadIdx.x, bi = blockIdx.x;
    int b = bi / NDIM, i = bi % NDIM;
    const float* src = G + (size_t)b * T3D * NDIM + i;
    for (int t = tid; t < LFFT; t += 512) {
        tws[t]  = g_twf[t];
        bufA[t] = make_float2(t < T3D ? src[(size_t)t * NDIM] : 0.f, 0.f);
    }
    __syncthreads();
    float2* res = fft1024(bufA, bufB, tws);
    float2* dst = g_ghat + (size_t)bi * FREQ;
    for (int f = tid; f < FREQ; f += 512) dst[f] = res[f];
}

__global__ __launch_bounds__(256)
void fgemm_kernel() {
    __shared__ float2 Gs[8][4][33];
    __shared__ float2 Ws[8][4][33];
    int f0 = blockIdx.x * 4, o0 = blockIdx.y * 32, tid = threadIdx.x;
    int tf = tid & 3, to = (tid >> 2) & 7, tb = tid >> 5;
    float2 acc[4][4];
#pragma unroll
    for (int i = 0; i < 4; i++)
#pragma unroll
        for (int j = 0; j < 4; j++) acc[i][j] = make_float2(0.f, 0.f);
    for (int i0 = 0; i0 < NDIM; i0 += 8) {
        for (int l = tid; l < 1024; l += 256) {
            int lf = l & 3, li = (l >> 2) & 7, lb = l >> 5;
            int f = f0 + lf, ii = i0 + li;
            float2 g = make_float2(0.f, 0.f), w = make_float2(0.f, 0.f);
            if (f < FREQ && ii < NDIM) {
                g = g_ghat[((size_t)lb * NDIM + ii) * FREQ + f];
                int o = o0 + lb;
                if (o < NDIM) w = g_what[((size_t)o * NDIM + ii) * FREQ + f];
            }
            Gs[li][lf][lb] = g;
            Ws[li][lf][lb] = w;
        }
        __syncthreads();
#pragma unroll
        for (int i2 = 0; i2 < 8; i2++) {
            float2 gv[4], wv[4];
#pragma unroll
            for (int q = 0; q < 4; q++) gv[q] = Gs[i2][tf][tb * 4 + q];
#pragma unroll
            for (int q = 0; q < 4; q++) wv[q] = Ws[i2][tf][to * 4 + q];
#pragma unroll
            for (int bi = 0; bi < 4; bi++)
#pragma unroll
                for (int oi = 0; oi < 4; oi++) {
                    acc[bi][oi].x += gv[bi].x * wv[oi].x + gv[bi].y * wv[oi].y;
                    acc[bi][oi].y += gv[bi].y * wv[oi].x - gv[bi].x * wv[oi].y;
                }
        }
        __syncthreads();
    }
    int f = f0 + tf;
    if (f >= FREQ) return;
#pragma unroll
    for (int bi = 0; bi < 4; bi++)
#pragma unroll
        for (int oi = 0; oi < 4; oi++) {
            int b = tb * 4 + bi, o = o0 + to * 4 + oi;
            if (o < NDIM)
                g_ohat[((size_t)b * NDIM + o) * FREQ + f] = acc[bi][oi];
        }
}

__global__ __launch_bounds__(512)
void ifft_kernel(const float* __restrict__ cb, float* __restrict__ outp) {
    __shared__ float2 bufA[LFFT], bufB[LFFT], tws[LFFT];
    int tid = threadIdx.x, bo = blockIdx.x;
    int o = bo % NDIM;
    const float2* src = g_ohat + (size_t)bo * FREQ;
    for (int f = tid; f < LFFT; f += 512) {
        tws[f] = g_twi[f];
        float2 v;
        if (f < FREQ) v = src[f];
        else { float2 u = src[LFFT - f]; v = make_float2(u.x, -u.y); }
        bufA[f] = v;
    }
    __syncthreads();
    float2* res = fft1024(bufA, bufB, tws);
    float bias = cb[o];
    for (int t = tid; t < T1D; t += 512)
        outp[(size_t)bo * T1D + t] = res[t].x * (1.f / 1024.f) + bias;
}

// ---------------- launch ----------------
extern "C" void kernel_launch(void* const* d_in, const int* in_sizes, int n_in,
                              void* d_out, int out_size) {
    const float* infeat = (const float*)d_in[0];
    const float* x    = (const float*)d_in[1];
    const float* w1   = (const float*)d_in[2];  const float* b1  = (const float*)d_in[3];
    const float* w11  = (const float*)d_in[4];  const float* b11 = (const float*)d_in[5];
    const float* w2   = (const float*)d_in[6];  const float* b2  = (const float*)d_in[7];
    const float* w22  = (const float*)d_in[8];  const float* b22 = (const float*)d_in[9];
    const float* w3   = (const float*)d_in[10]; const float* b3  = (const float*)d_in[11];
    const float* w33  = (const float*)d_in[12]; const float* b33 = (const float*)d_in[13];
    const float* cw   = (const float*)d_in[14]; const float* cb  = (const float*)d_in[15];
    const int*   week = (const int*)d_in[16];   const int*   hour = (const int*)d_in[17];
    float* outp = (float*)d_out;

    float *buf0, *buf1, *s1, *s2;
    __nv_bfloat16 *ah0, *al0, *ah1, *al1, *wth, *wtl;
    cudaGetSymbolAddress((void**)&buf0, g_buf0);
    cudaGetSymbolAddress((void**)&buf1, g_buf1);
    cudaGetSymbolAddress((void**)&s1,   g_s1);
    cudaGetSymbolAddress((void**)&s2,   g_s2);
    cudaGetSymbolAddress((void**)&ah0,  g_ah0);
    cudaGetSymbolAddress((void**)&al0,  g_al0);
    cudaGetSymbolAddress((void**)&ah1,  g_ah1);
    cudaGetSymbolAddress((void**)&al1,  g_al1);
    cudaGetSymbolAddress((void**)&wth,  g_wth);
    cudaGetSymbolAddress((void**)&wtl,  g_wtl);

    cudaFuncSetAttribute(gemm_mma, cudaFuncAttributeMaxDynamicSharedMemorySize, MMA_SMEM);

    const int pb = (MROWS * KP + 255) / 256;
    dim3 gG(MROWS / 128, (NDIM + 63) / 64);

    init_tw_kernel<<<2, 512>>>();
    W6 wp; wp.p[0] = w1; wp.p[1] = w11; wp.p[2] = w2; wp.p[3] = w22; wp.p[4] = w3; wp.p[5] = w33;
    wsplit_kernel<<<(6 * KP * KP + 255) / 256, 256>>>(wp);
    gather_split_kernel<<<pb, 256>>>(infeat, x, week, hour);

    const size_t WS = (size_t)KP * KP;
    gemm_mma<<<gG, 256, MMA_SMEM>>>(ah0, al0, wth + 0 * WS, wtl + 0 * WS, s1);
    gemm_mma<<<gG, 256, MMA_SMEM>>>(ah0, al0, wth + 1 * WS, wtl + 1 * WS, s2);
    stencil_split_kernel<<<pb, 256>>>(s1, s2, b1, b11, buf1, ah1, al1);

    gemm_mma<<<gG, 256, MMA_SMEM>>>(ah1, al1, wth + 2 * WS, wtl + 2 * WS, s1);
    gemm_mma<<<gG, 256, MMA_SMEM>>>(ah1, al1, wth + 3 * WS, wtl + 3 * WS, s2);
    stencil_split_kernel<<<pb, 256>>>(s1, s2, b2, b22, buf0, ah0, al0);

    gemm_mma<<<gG, 256, MMA_SMEM>>>(ah0, al0, wth + 4 * WS, wtl + 4 * WS, s1);
    gemm_mma<<<gG, 256, MMA_SMEM>>>(ah0, al0, wth + 5 * WS, wtl + 5 * WS, s2);
    stencil_split_kernel<<<pb, 256>>>(s1, s2, b3, b33, buf1, ah1, al1);

    fft_g_kernel<<<BATCH * NDIM, 512>>>(buf1);
    fft_w_kernel<<<NDIM * NDIM, 512>>>(cw);
    fgemm_kernel<<<dim3((FREQ + 3) / 4, (NDIM + 31) / 32), 256>>>();
    ifft_kernel<<<BATCH * NDIM, 512>>>(cb, outp);
}